// round 6
// baseline (speedup 1.0000x reference)
#include <cuda_runtime.h>
#include <cuda_bf16.h>
#include <cstdint>

// ---------------------------------------------------------------------------
// LocalWindowTransformer on sm_103 (mma.sync HMMA path).
//   GEMM1: qkv = x @ Win^T + b_in   [16384 x 3072], K=1024
//   attn : per (window, head) online-softmax(qk^T/8)v  (fp32 FFMA2)
//   GEMM3: out = att @ Wout^T + b_out [16384 x 1024], K=1024
// fp32 GEMM emulated with bf16 3-split: A_hi*B_hi + A_hi*B_lo + A_lo*B_hi,
// fp32 accumulate in mma.sync.m16n8k16.row.col.f32.bf16.bf16.f32.
// R4: 3-stage cp.async pipeline (1 barrier/tile), flash-style attention.
// ---------------------------------------------------------------------------

#define M_TOK   16384
#define HDIM    1024
#define QKVDIM  3072
#define NHEAD   16
#define HD      64
#define WIN     128
#define NWIN    128

// ---- device scratch (no cudaMalloc allowed) --------------------------------
__device__ float  g_qkv [(size_t)M_TOK * QKVDIM];          // 192 MiB fp32
__device__ uint4  g_xh  [(size_t)M_TOK * HDIM / 8];        // 32 MiB bf16
__device__ uint4  g_xl  [(size_t)M_TOK * HDIM / 8];
__device__ uint4  g_wih [(size_t)QKVDIM * HDIM / 8];       // 6 MiB
__device__ uint4  g_wil [(size_t)QKVDIM * HDIM / 8];
__device__ uint4  g_woh [(size_t)HDIM * HDIM / 8];         // 2 MiB
__device__ uint4  g_wol [(size_t)HDIM * HDIM / 8];
__device__ uint4  g_ah  [(size_t)M_TOK * HDIM / 8];        // 32 MiB (attn out)
__device__ uint4  g_al  [(size_t)M_TOK * HDIM / 8];

// ---- helpers ---------------------------------------------------------------
__device__ __forceinline__ uint32_t smem_u32(const void* p) {
    uint32_t a;
    asm("{ .reg .u64 t; cvta.to.shared.u64 t, %1; cvt.u32.u64 %0, t; }"
        : "=r"(a) : "l"(p));
    return a;
}
__device__ __forceinline__ void cp16(uint32_t dst, const void* src) {
    asm volatile("cp.async.cg.shared.global [%0], [%1], 16;"
                 :: "r"(dst), "l"(src));
}

#define LDSM4(r, a) \
    asm volatile("ldmatrix.sync.aligned.m8n8.x4.shared.b16 {%0,%1,%2,%3}, [%4];" \
                 : "=r"((r)[0]), "=r"((r)[1]), "=r"((r)[2]), "=r"((r)[3]) \
                 : "r"(a))

#define MMA(c, a, b0, b1) \
    asm volatile("mma.sync.aligned.m16n8k16.row.col.f32.bf16.bf16.f32 " \
                 "{%0,%1,%2,%3}, {%4,%5,%6,%7}, {%8,%9}, {%0,%1,%2,%3};" \
                 : "+f"((c)[0]), "+f"((c)[1]), "+f"((c)[2]), "+f"((c)[3]) \
                 : "r"((a)[0]), "r"((a)[1]), "r"((a)[2]), "r"((a)[3]), \
                   "r"(b0), "r"(b1))

union U8 { uint4 q; __nv_bfloat16 b[8]; };

// ---------------------------------------------------------------------------
// split fp32 row-major -> bf16 hi/lo row-major. 1 thread = 8 values.
// ---------------------------------------------------------------------------
__global__ __launch_bounds__(256)
void split_rm(const float4* __restrict__ src,
              uint4* __restrict__ hi, uint4* __restrict__ lo)
{
    int u = blockIdx.x * 256 + threadIdx.x;
    float4 a = src[2 * u], b = src[2 * u + 1];
    float v[8] = {a.x, a.y, a.z, a.w, b.x, b.y, b.z, b.w};
    U8 H, L;
#pragma unroll
    for (int j = 0; j < 8; ++j) {
        __nv_bfloat16 hb = __float2bfloat16(v[j]);
        H.b[j] = hb;
        L.b[j] = __float2bfloat16(v[j] - __bfloat162float(hb));
    }
    hi[u] = H.q;
    lo[u] = L.q;
}

// ---------------------------------------------------------------------------
// HMMA NT GEMM: C[M,N] = A[M,1024] * B[N,1024]^T + bias (fp32 via bf16 split)
// BM=BN=128, BK=32, 256 threads (8 warps, 2x4), warp tile 64x32.
// smem rows padded to 80B. 3-stage cp.async pipeline, ONE barrier per tile.
// ---------------------------------------------------------------------------
#define ARR    10240            /* one 128x32 bf16 array, 80B rows */
#define STAGE  40960            /* Ah|Al|Bh|Bl */
#define KT     32               /* 1024 / 32 */
#define GEMM_SMEM (3 * STAGE)   /* 122880 B */

__global__ __launch_bounds__(256, 1)
void gemm_mma(const __nv_bfloat16* __restrict__ Ah,
              const __nv_bfloat16* __restrict__ Al,
              const __nv_bfloat16* __restrict__ Bh,
              const __nv_bfloat16* __restrict__ Bl,
              const float* __restrict__ bias,
              float* __restrict__ C, int N)
{
    extern __shared__ char smem_raw[];
    const uint32_t sb = smem_u32(smem_raw);

    const int tid  = threadIdx.x;
    const int lane = tid & 31;
    const int wid  = tid >> 5;
    const int wm   = wid & 1;           // 0..1  (64-row halves)
    const int wn   = wid >> 1;          // 0..3  (32-col quarters)
    const int bm   = blockIdx.x;
    const int bn   = blockIdx.y;

    // --- per-thread load slots: 2 units per array, unit = 16B ---
    const int r0 = tid >> 2;                 // rows 0..63
    const int r1 = r0 + 64;                  // rows 64..127
    const int ce = (tid & 3) * 8;            // bf16 element offset of chunk
    const uint32_t d0 = r0 * 80 + (tid & 3) * 16;
    const uint32_t d1 = r1 * 80 + (tid & 3) * 16;

    const __nv_bfloat16* pAh0 = Ah + (size_t)(bm * 128 + r0) * 1024 + ce;
    const __nv_bfloat16* pAh1 = Ah + (size_t)(bm * 128 + r1) * 1024 + ce;
    const __nv_bfloat16* pAl0 = Al + (size_t)(bm * 128 + r0) * 1024 + ce;
    const __nv_bfloat16* pAl1 = Al + (size_t)(bm * 128 + r1) * 1024 + ce;
    const __nv_bfloat16* pBh0 = Bh + (size_t)(bn * 128 + r0) * 1024 + ce;
    const __nv_bfloat16* pBh1 = Bh + (size_t)(bn * 128 + r1) * 1024 + ce;
    const __nv_bfloat16* pBl0 = Bl + (size_t)(bn * 128 + r0) * 1024 + ce;
    const __nv_bfloat16* pBl1 = Bl + (size_t)(bn * 128 + r1) * 1024 + ce;

    // --- per-thread ldmatrix bases ---
    const uint32_t a_off = (uint32_t)((wm * 64 + (lane & 15)) * 80 + (lane >> 4) * 16);
    const uint32_t b_off = (uint32_t)(2 * ARR + (wn * 32 + (lane & 15)) * 80 + (lane >> 4) * 16);

    float acc[4][4][4];
#pragma unroll
    for (int i = 0; i < 4; ++i)
#pragma unroll
        for (int j = 0; j < 4; ++j)
#pragma unroll
            for (int k = 0; k < 4; ++k) acc[i][j][k] = 0.f;

    // --- issue one stage's loads into smem slot ---
    auto issue = [&](uint32_t st, int ko) {
        cp16(st + d0,         pAh0 + ko); cp16(st + d1,         pAh1 + ko);
        cp16(st + ARR + d0,   pAl0 + ko); cp16(st + ARR + d1,   pAl1 + ko);
        cp16(st + 2*ARR + d0, pBh0 + ko); cp16(st + 2*ARR + d1, pBh1 + ko);
        cp16(st + 3*ARR + d0, pBl0 + ko); cp16(st + 3*ARR + d1, pBl1 + ko);
    };

    // prologue: stages 0 and 1
    issue(sb, 0);
    asm volatile("cp.async.commit_group;" ::: "memory");
    issue(sb + STAGE, 32);
    asm volatile("cp.async.commit_group;" ::: "memory");

    int cs = 0;       // compute slot
    int ws = 2;       // write slot (stage t+2)
    for (int t = 0; t < KT; ++t) {
        // stage t arrived (newest pending group allowed: stage t+1)
        asm volatile("cp.async.wait_group 1;" ::: "memory");
        __syncthreads();   // all warps done with stage t-1's slot; data visible

        if (t + 2 < KT)
            issue(sb + ws * STAGE, (t + 2) * 32);
        asm volatile("cp.async.commit_group;" ::: "memory");
        ws = (ws == 2) ? 0 : ws + 1;

        const uint32_t st = sb + cs * STAGE;
        cs = (cs == 2) ? 0 : cs + 1;
        const uint32_t ab = st + a_off;
        const uint32_t bb = st + b_off;
#pragma unroll
        for (int ks = 0; ks < 2; ++ks) {
            uint32_t ah[4][4], al[4][4], bh[2][4], bl[2][4];
#pragma unroll
            for (int mt = 0; mt < 4; ++mt) {
                LDSM4(ah[mt], ab + mt * 1280 + ks * 32);
                LDSM4(al[mt], ab + ARR + mt * 1280 + ks * 32);
            }
#pragma unroll
            for (int np = 0; np < 2; ++np) {
                LDSM4(bh[np], bb + np * 1280 + ks * 32);
                LDSM4(bl[np], bb + ARR + np * 1280 + ks * 32);
            }
#pragma unroll
            for (int mt = 0; mt < 4; ++mt) {
#pragma unroll
                for (int nt = 0; nt < 4; ++nt) {
                    const int np = nt >> 1, s = nt & 1;
                    MMA(acc[mt][nt], ah[mt], bh[np][s], bh[np][s + 2]);
                    MMA(acc[mt][nt], ah[mt], bl[np][s], bl[np][s + 2]);
                    MMA(acc[mt][nt], al[mt], bh[np][s], bh[np][s + 2]);
                }
            }
        }
    }

    // --- epilogue: register frags -> GMEM with bias ---
#pragma unroll
    for (int mt = 0; mt < 4; ++mt) {
#pragma unroll
        for (int nt = 0; nt < 4; ++nt) {
            const float* c = acc[mt][nt];
            const int row = bm * 128 + wm * 64 + mt * 16 + (lane >> 2);
            const int col = bn * 128 + wn * 32 + nt * 8 + (lane & 3) * 2;
            const float b0 = __ldg(bias + col);
            const float b1 = __ldg(bias + col + 1);
            *(float2*)(C + (size_t)row * N + col) =
                make_float2(c[0] + b0, c[1] + b1);
            *(float2*)(C + (size_t)(row + 8) * N + col) =
                make_float2(c[2] + b0, c[3] + b1);
        }
    }
}

// ---------------------------------------------------------------------------
// Windowed attention: online (chunked flash) softmax, fp32 packed-f32x2 math.
// One CTA per (window, head), 128 threads, thread = query row. smem = K+V only
// (64 KB) -> up to 3 CTAs/SM.
// ---------------------------------------------------------------------------
__device__ __forceinline__ unsigned long long pk2(float lo, float hi) {
    unsigned long long r;
    asm("mov.b64 %0, {%1, %2};" : "=l"(r) : "f"(lo), "f"(hi));
    return r;
}
__device__ __forceinline__ void upk2(float& lo, float& hi, unsigned long long v) {
    asm("mov.b64 {%0, %1}, %2;" : "=f"(lo), "=f"(hi) : "l"(v));
}
__device__ __forceinline__ void ffma2(unsigned long long& c,
                                      unsigned long long a,
                                      unsigned long long b) {
    asm("fma.rn.f32x2 %0, %1, %2, %0;" : "+l"(c) : "l"(a), "l"(b));
}
__device__ __forceinline__ void fmul2(unsigned long long& c,
                                      unsigned long long a) {
    asm("mul.rn.f32x2 %0, %0, %1;" : "+l"(c) : "l"(a));
}

#define ATTN_SMEM ((8192 + 8192) * 4)

__global__ __launch_bounds__(128)
void attn_kernel(const float* __restrict__ qkv,
                 uint4* __restrict__ oh, uint4* __restrict__ ol)
{
    extern __shared__ float sm[];
    float* Ks = sm;               // [128][64]
    float* Vs = sm + 8192;        // [128][64]

    const int w    = blockIdx.x;
    const int hd_i = blockIdx.y;
    const int tid  = threadIdx.x;

    const size_t base = (size_t)w * WIN * QKVDIM;
    const float* Kg = qkv + base + HDIM     + hd_i * HD;
    const float* Vg = qkv + base + 2 * HDIM + hd_i * HD;

    for (int idx = tid; idx < WIN * HD; idx += 128) {
        int row = idx >> 6, d = idx & 63;
        Ks[idx] = Kg[(size_t)row * QKVDIM + d];
        Vs[idx] = Vg[(size_t)row * QKVDIM + d];
    }

    const float4* Qg = (const float4*)(qkv + base + (size_t)tid * QKVDIM + hd_i * HD);
    unsigned long long q2[32];
#pragma unroll
    for (int i = 0; i < 16; ++i) {
        float4 v = Qg[i];
        q2[2*i]   = pk2(v.x, v.y);
        q2[2*i+1] = pk2(v.z, v.w);
    }
    __syncthreads();

    const unsigned long long* K2 = (const unsigned long long*)Ks;
    const unsigned long long* V2 = (const unsigned long long*)Vs;

    float m = -1e30f, l = 0.f;
    unsigned long long o2[32];
#pragma unroll
    for (int d = 0; d < 32; ++d) o2[d] = 0ull;

    for (int c = 0; c < 8; ++c) {             // 8 chunks of 16 keys
        float s[16];
#pragma unroll
        for (int jj = 0; jj < 16; ++jj) {
            const int j = c * 16 + jj;
            unsigned long long a0 = 0, a1 = 0, a2 = 0, a3 = 0;
            const unsigned long long* kj = K2 + j * 32;
#pragma unroll
            for (int d = 0; d < 32; d += 4) {
                ffma2(a0, q2[d+0], kj[d+0]);
                ffma2(a1, q2[d+1], kj[d+1]);
                ffma2(a2, q2[d+2], kj[d+2]);
                ffma2(a3, q2[d+3], kj[d+3]);
            }
            float lo, hi, ss;
            upk2(lo, hi, a0); ss  = lo + hi;
            upk2(lo, hi, a1); ss += lo + hi;
            upk2(lo, hi, a2); ss += lo + hi;
            upk2(lo, hi, a3); ss += lo + hi;
            s[jj] = ss * 0.125f;
        }
        float cm = s[0];
#pragma unroll
        for (int jj = 1; jj < 16; ++jj) cm = fmaxf(cm, s[jj]);
        const float nm = fmaxf(m, cm);
        const float sc = __expf(m - nm);
        m = nm;
        l *= sc;
        const unsigned long long sc2 = pk2(sc, sc);
#pragma unroll
        for (int d = 0; d < 32; ++d) fmul2(o2[d], sc2);
#pragma unroll
        for (int jj = 0; jj < 16; ++jj) {
            const float p = __expf(s[jj] - nm);
            l += p;
            const unsigned long long p2 = pk2(p, p);
            const unsigned long long* vj = V2 + (c * 16 + jj) * 32;
#pragma unroll
            for (int d = 0; d < 32; ++d) ffma2(o2[d], p2, vj[d]);
        }
    }

    const float inv = 1.0f / l;
    float ov[64];
#pragma unroll
    for (int d = 0; d < 32; ++d) {
        float lo, hi; upk2(lo, hi, o2[d]);
        ov[2*d]   = lo * inv;
        ov[2*d+1] = hi * inv;
    }

    // bf16 hi/lo split, row-major [M_TOK, 1024]
    const size_t obase = ((size_t)(w * WIN + tid) * HDIM + hd_i * HD) >> 3;
#pragma unroll
    for (int c8 = 0; c8 < 8; ++c8) {
        U8 H, L;
#pragma unroll
        for (int j = 0; j < 8; ++j) {
            float v = ov[c8 * 8 + j];
            __nv_bfloat16 hb = __float2bfloat16(v);
            H.b[j] = hb;
            L.b[j] = __float2bfloat16(v - __bfloat162float(hb));
        }
        oh[obase + c8] = H.q;
        ol[obase + c8] = L.q;
    }
}

// ---------------------------------------------------------------------------
extern "C" void kernel_launch(void* const* d_in, const int* in_sizes, int n_in,
                              void* d_out, int out_size)
{
    (void)in_sizes; (void)n_in; (void)out_size;
    const float* x     = (const float*)d_in[0];
    const float* w_in  = (const float*)d_in[1];
    const float* b_in  = (const float*)d_in[2];
    const float* w_out = (const float*)d_in[3];
    const float* b_out = (const float*)d_in[4];
    float* out = (float*)d_out;

    float* qkv;
    uint4 *xh, *xl, *wih, *wil, *woh, *wol, *ah, *al;
    cudaGetSymbolAddress((void**)&qkv, g_qkv);
    cudaGetSymbolAddress((void**)&xh,  g_xh);
    cudaGetSymbolAddress((void**)&xl,  g_xl);
    cudaGetSymbolAddress((void**)&wih, g_wih);
    cudaGetSymbolAddress((void**)&wil, g_wil);
    cudaGetSymbolAddress((void**)&woh, g_woh);
    cudaGetSymbolAddress((void**)&wol, g_wol);
    cudaGetSymbolAddress((void**)&ah,  g_ah);
    cudaGetSymbolAddress((void**)&al,  g_al);

    cudaFuncSetAttribute(gemm_mma,
                         cudaFuncAttributeMaxDynamicSharedMemorySize, GEMM_SMEM);
    cudaFuncSetAttribute(attn_kernel,
                         cudaFuncAttributeMaxDynamicSharedMemorySize, ATTN_SMEM);

    // split fp32 inputs into bf16 hi/lo (row-major)
    split_rm<<<(M_TOK  * HDIM) / 2048, 256>>>((const float4*)x,     xh,  xl);
    split_rm<<<(QKVDIM * HDIM) / 2048, 256>>>((const float4*)w_in,  wih, wil);
    split_rm<<<(HDIM   * HDIM) / 2048, 256>>>((const float4*)w_out, woh, wol);

    // Stage 1: QKV projection
    gemm_mma<<<dim3(M_TOK / 128, QKVDIM / 128), 256, GEMM_SMEM>>>(
        (const __nv_bfloat16*)xh, (const __nv_bfloat16*)xl,
        (const __nv_bfloat16*)wih, (const __nv_bfloat16*)wil,
        b_in, qkv, QKVDIM);

    // Stage 2: windowed attention (online softmax, emits bf16 hi/lo)
    attn_kernel<<<dim3(NWIN, NHEAD), 128, ATTN_SMEM>>>(qkv, ah, al);

    // Stage 3: output projection
    gemm_mma<<<dim3(M_TOK / 128, HDIM / 128), 256, GEMM_SMEM>>>(
        (const __nv_bfloat16*)ah, (const __nv_bfloat16*)al,
        (const __nv_bfloat16*)woh, (const __nv_bfloat16*)wol,
        b_out, out, HDIM);
}

// round 7
// speedup vs baseline: 1.0028x; 1.0028x over previous
#include <cuda_runtime.h>
#include <cuda_bf16.h>
#include <cstdint>

// ---------------------------------------------------------------------------
// LocalWindowTransformer on sm_103 (mma.sync HMMA path).
//   GEMM1: qkv = x @ Win^T + b_in   [16384 x 3072], K=1024
//   attn : per (window, head) online-softmax(qk^T/8)v  (fp32 FFMA2)
//   GEMM3: out = att @ Wout^T + b_out [16384 x 1024], K=1024
// fp32 GEMM emulated with bf16 3-split: A_hi*B_hi + A_hi*B_lo + A_lo*B_hi,
// fp32 accumulate in mma.sync.m16n8k16.row.col.f32.bf16.bf16.f32.
// R4: 3-stage cp.async pipeline (1 barrier/tile), flash-style attention.
// ---------------------------------------------------------------------------

#define M_TOK   16384
#define HDIM    1024
#define QKVDIM  3072
#define NHEAD   16
#define HD      64
#define WIN     128
#define NWIN    128

// ---- device scratch (no cudaMalloc allowed) --------------------------------
__device__ float  g_qkv [(size_t)M_TOK * QKVDIM];          // 192 MiB fp32
__device__ uint4  g_xh  [(size_t)M_TOK * HDIM / 8];        // 32 MiB bf16
__device__ uint4  g_xl  [(size_t)M_TOK * HDIM / 8];
__device__ uint4  g_wih [(size_t)QKVDIM * HDIM / 8];       // 6 MiB
__device__ uint4  g_wil [(size_t)QKVDIM * HDIM / 8];
__device__ uint4  g_woh [(size_t)HDIM * HDIM / 8];         // 2 MiB
__device__ uint4  g_wol [(size_t)HDIM * HDIM / 8];
__device__ uint4  g_ah  [(size_t)M_TOK * HDIM / 8];        // 32 MiB (attn out)
__device__ uint4  g_al  [(size_t)M_TOK * HDIM / 8];

// ---- helpers ---------------------------------------------------------------
__device__ __forceinline__ uint32_t smem_u32(const void* p) {
    uint32_t a;
    asm("{ .reg .u64 t; cvta.to.shared.u64 t, %1; cvt.u32.u64 %0, t; }"
        : "=r"(a) : "l"(p));
    return a;
}
__device__ __forceinline__ void cp16(uint32_t dst, const void* src) {
    asm volatile("cp.async.cg.shared.global [%0], [%1], 16;"
                 :: "r"(dst), "l"(src));
}

#define LDSM4(r, a) \
    asm volatile("ldmatrix.sync.aligned.m8n8.x4.shared.b16 {%0,%1,%2,%3}, [%4];" \
                 : "=r"((r)[0]), "=r"((r)[1]), "=r"((r)[2]), "=r"((r)[3]) \
                 : "r"(a))

#define MMA(c, a, b0, b1) \
    asm volatile("mma.sync.aligned.m16n8k16.row.col.f32.bf16.bf16.f32 " \
                 "{%0,%1,%2,%3}, {%4,%5,%6,%7}, {%8,%9}, {%0,%1,%2,%3};" \
                 : "+f"((c)[0]), "+f"((c)[1]), "+f"((c)[2]), "+f"((c)[3]) \
                 : "r"((a)[0]), "r"((a)[1]), "r"((a)[2]), "r"((a)[3]), \
                   "r"(b0), "r"(b1))

union U8 { uint4 q; __nv_bfloat16 b[8]; };

// ---------------------------------------------------------------------------
// split fp32 row-major -> bf16 hi/lo row-major. 1 thread = 8 values.
// ---------------------------------------------------------------------------
__global__ __launch_bounds__(256)
void split_rm(const float4* __restrict__ src,
              uint4* __restrict__ hi, uint4* __restrict__ lo)
{
    int u = blockIdx.x * 256 + threadIdx.x;
    float4 a = src[2 * u], b = src[2 * u + 1];
    float v[8] = {a.x, a.y, a.z, a.w, b.x, b.y, b.z, b.w};
    U8 H, L;
#pragma unroll
    for (int j = 0; j < 8; ++j) {
        __nv_bfloat16 hb = __float2bfloat16(v[j]);
        H.b[j] = hb;
        L.b[j] = __float2bfloat16(v[j] - __bfloat162float(hb));
    }
    hi[u] = H.q;
    lo[u] = L.q;
}

// ---------------------------------------------------------------------------
// HMMA NT GEMM: C[M,N] = A[M,1024] * B[N,1024]^T + bias (fp32 via bf16 split)
// BM=BN=128, BK=32, 256 threads (8 warps, 2x4), warp tile 64x32.
// smem rows padded to 80B. 3-stage cp.async pipeline, ONE barrier per tile.
// ---------------------------------------------------------------------------
#define ARR    10240            /* one 128x32 bf16 array, 80B rows */
#define STAGE  40960            /* Ah|Al|Bh|Bl */
#define KT     32               /* 1024 / 32 */
#define GEMM_SMEM (3 * STAGE)   /* 122880 B */

__global__ __launch_bounds__(256, 1)
void gemm_mma(const __nv_bfloat16* __restrict__ Ah,
              const __nv_bfloat16* __restrict__ Al,
              const __nv_bfloat16* __restrict__ Bh,
              const __nv_bfloat16* __restrict__ Bl,
              const float* __restrict__ bias,
              float* __restrict__ C, int N)
{
    extern __shared__ char smem_raw[];
    const uint32_t sb = smem_u32(smem_raw);

    const int tid  = threadIdx.x;
    const int lane = tid & 31;
    const int wid  = tid >> 5;
    const int wm   = wid & 1;           // 0..1  (64-row halves)
    const int wn   = wid >> 1;          // 0..3  (32-col quarters)
    const int bm   = blockIdx.x;
    const int bn   = blockIdx.y;

    // --- per-thread load slots: 2 units per array, unit = 16B ---
    const int r0 = tid >> 2;                 // rows 0..63
    const int r1 = r0 + 64;                  // rows 64..127
    const int ce = (tid & 3) * 8;            // bf16 element offset of chunk
    const uint32_t d0 = r0 * 80 + (tid & 3) * 16;
    const uint32_t d1 = r1 * 80 + (tid & 3) * 16;

    const __nv_bfloat16* pAh0 = Ah + (size_t)(bm * 128 + r0) * 1024 + ce;
    const __nv_bfloat16* pAh1 = Ah + (size_t)(bm * 128 + r1) * 1024 + ce;
    const __nv_bfloat16* pAl0 = Al + (size_t)(bm * 128 + r0) * 1024 + ce;
    const __nv_bfloat16* pAl1 = Al + (size_t)(bm * 128 + r1) * 1024 + ce;
    const __nv_bfloat16* pBh0 = Bh + (size_t)(bn * 128 + r0) * 1024 + ce;
    const __nv_bfloat16* pBh1 = Bh + (size_t)(bn * 128 + r1) * 1024 + ce;
    const __nv_bfloat16* pBl0 = Bl + (size_t)(bn * 128 + r0) * 1024 + ce;
    const __nv_bfloat16* pBl1 = Bl + (size_t)(bn * 128 + r1) * 1024 + ce;

    // --- per-thread ldmatrix bases ---
    const uint32_t a_off = (uint32_t)((wm * 64 + (lane & 15)) * 80 + (lane >> 4) * 16);
    const uint32_t b_off = (uint32_t)(2 * ARR + (wn * 32 + (lane & 15)) * 80 + (lane >> 4) * 16);

    float acc[4][4][4];
#pragma unroll
    for (int i = 0; i < 4; ++i)
#pragma unroll
        for (int j = 0; j < 4; ++j)
#pragma unroll
            for (int k = 0; k < 4; ++k) acc[i][j][k] = 0.f;

    // --- issue one stage's loads into smem slot ---
    auto issue = [&](uint32_t st, int ko) {
        cp16(st + d0,         pAh0 + ko); cp16(st + d1,         pAh1 + ko);
        cp16(st + ARR + d0,   pAl0 + ko); cp16(st + ARR + d1,   pAl1 + ko);
        cp16(st + 2*ARR + d0, pBh0 + ko); cp16(st + 2*ARR + d1, pBh1 + ko);
        cp16(st + 3*ARR + d0, pBl0 + ko); cp16(st + 3*ARR + d1, pBl1 + ko);
    };

    // prologue: stages 0 and 1
    issue(sb, 0);
    asm volatile("cp.async.commit_group;" ::: "memory");
    issue(sb + STAGE, 32);
    asm volatile("cp.async.commit_group;" ::: "memory");

    int cs = 0;       // compute slot
    int ws = 2;       // write slot (stage t+2)
    for (int t = 0; t < KT; ++t) {
        // stage t arrived (newest pending group allowed: stage t+1)
        asm volatile("cp.async.wait_group 1;" ::: "memory");
        __syncthreads();   // all warps done with stage t-1's slot; data visible

        if (t + 2 < KT)
            issue(sb + ws * STAGE, (t + 2) * 32);
        asm volatile("cp.async.commit_group;" ::: "memory");
        ws = (ws == 2) ? 0 : ws + 1;

        const uint32_t st = sb + cs * STAGE;
        cs = (cs == 2) ? 0 : cs + 1;
        const uint32_t ab = st + a_off;
        const uint32_t bb = st + b_off;
#pragma unroll
        for (int ks = 0; ks < 2; ++ks) {
            uint32_t ah[4][4], al[4][4], bh[2][4], bl[2][4];
#pragma unroll
            for (int mt = 0; mt < 4; ++mt) {
                LDSM4(ah[mt], ab + mt * 1280 + ks * 32);
                LDSM4(al[mt], ab + ARR + mt * 1280 + ks * 32);
            }
#pragma unroll
            for (int np = 0; np < 2; ++np) {
                LDSM4(bh[np], bb + np * 1280 + ks * 32);
                LDSM4(bl[np], bb + ARR + np * 1280 + ks * 32);
            }
#pragma unroll
            for (int mt = 0; mt < 4; ++mt) {
#pragma unroll
                for (int nt = 0; nt < 4; ++nt) {
                    const int np = nt >> 1, s = nt & 1;
                    MMA(acc[mt][nt], ah[mt], bh[np][s], bh[np][s + 2]);
                    MMA(acc[mt][nt], ah[mt], bl[np][s], bl[np][s + 2]);
                    MMA(acc[mt][nt], al[mt], bh[np][s], bh[np][s + 2]);
                }
            }
        }
    }

    // --- epilogue: register frags -> GMEM with bias ---
#pragma unroll
    for (int mt = 0; mt < 4; ++mt) {
#pragma unroll
        for (int nt = 0; nt < 4; ++nt) {
            const float* c = acc[mt][nt];
            const int row = bm * 128 + wm * 64 + mt * 16 + (lane >> 2);
            const int col = bn * 128 + wn * 32 + nt * 8 + (lane & 3) * 2;
            const float b0 = __ldg(bias + col);
            const float b1 = __ldg(bias + col + 1);
            *(float2*)(C + (size_t)row * N + col) =
                make_float2(c[0] + b0, c[1] + b1);
            *(float2*)(C + (size_t)(row + 8) * N + col) =
                make_float2(c[2] + b0, c[3] + b1);
        }
    }
}

// ---------------------------------------------------------------------------
// Windowed attention: online (chunked flash) softmax, fp32 packed-f32x2 math.
// One CTA per (window, head), 128 threads, thread = query row. smem = K+V only
// (64 KB) -> up to 3 CTAs/SM.
// ---------------------------------------------------------------------------
__device__ __forceinline__ unsigned long long pk2(float lo, float hi) {
    unsigned long long r;
    asm("mov.b64 %0, {%1, %2};" : "=l"(r) : "f"(lo), "f"(hi));
    return r;
}
__device__ __forceinline__ void upk2(float& lo, float& hi, unsigned long long v) {
    asm("mov.b64 {%0, %1}, %2;" : "=f"(lo), "=f"(hi) : "l"(v));
}
__device__ __forceinline__ void ffma2(unsigned long long& c,
                                      unsigned long long a,
                                      unsigned long long b) {
    asm("fma.rn.f32x2 %0, %1, %2, %0;" : "+l"(c) : "l"(a), "l"(b));
}
__device__ __forceinline__ void fmul2(unsigned long long& c,
                                      unsigned long long a) {
    asm("mul.rn.f32x2 %0, %0, %1;" : "+l"(c) : "l"(a));
}

#define ATTN_SMEM ((8192 + 8192) * 4)

__global__ __launch_bounds__(128)
void attn_kernel(const float* __restrict__ qkv,
                 uint4* __restrict__ oh, uint4* __restrict__ ol)
{
    extern __shared__ float sm[];
    float* Ks = sm;               // [128][64]
    float* Vs = sm + 8192;        // [128][64]

    const int w    = blockIdx.x;
    const int hd_i = blockIdx.y;
    const int tid  = threadIdx.x;

    const size_t base = (size_t)w * WIN * QKVDIM;
    const float* Kg = qkv + base + HDIM     + hd_i * HD;
    const float* Vg = qkv + base + 2 * HDIM + hd_i * HD;

    for (int idx = tid; idx < WIN * HD; idx += 128) {
        int row = idx >> 6, d = idx & 63;
        Ks[idx] = Kg[(size_t)row * QKVDIM + d];
        Vs[idx] = Vg[(size_t)row * QKVDIM + d];
    }

    const float4* Qg = (const float4*)(qkv + base + (size_t)tid * QKVDIM + hd_i * HD);
    unsigned long long q2[32];
#pragma unroll
    for (int i = 0; i < 16; ++i) {
        float4 v = Qg[i];
        q2[2*i]   = pk2(v.x, v.y);
        q2[2*i+1] = pk2(v.z, v.w);
    }
    __syncthreads();

    const unsigned long long* K2 = (const unsigned long long*)Ks;
    const unsigned long long* V2 = (const unsigned long long*)Vs;

    float m = -1e30f, l = 0.f;
    unsigned long long o2[32];
#pragma unroll
    for (int d = 0; d < 32; ++d) o2[d] = 0ull;

    for (int c = 0; c < 8; ++c) {             // 8 chunks of 16 keys
        float s[16];
#pragma unroll
        for (int jj = 0; jj < 16; ++jj) {
            const int j = c * 16 + jj;
            unsigned long long a0 = 0, a1 = 0, a2 = 0, a3 = 0;
            const unsigned long long* kj = K2 + j * 32;
#pragma unroll
            for (int d = 0; d < 32; d += 4) {
                ffma2(a0, q2[d+0], kj[d+0]);
                ffma2(a1, q2[d+1], kj[d+1]);
                ffma2(a2, q2[d+2], kj[d+2]);
                ffma2(a3, q2[d+3], kj[d+3]);
            }
            float lo, hi, ss;
            upk2(lo, hi, a0); ss  = lo + hi;
            upk2(lo, hi, a1); ss += lo + hi;
            upk2(lo, hi, a2); ss += lo + hi;
            upk2(lo, hi, a3); ss += lo + hi;
            s[jj] = ss * 0.125f;
        }
        float cm = s[0];
#pragma unroll
        for (int jj = 1; jj < 16; ++jj) cm = fmaxf(cm, s[jj]);
        const float nm = fmaxf(m, cm);
        const float sc = __expf(m - nm);
        m = nm;
        l *= sc;
        const unsigned long long sc2 = pk2(sc, sc);
#pragma unroll
        for (int d = 0; d < 32; ++d) fmul2(o2[d], sc2);
#pragma unroll
        for (int jj = 0; jj < 16; ++jj) {
            const float p = __expf(s[jj] - nm);
            l += p;
            const unsigned long long p2 = pk2(p, p);
            const unsigned long long* vj = V2 + (c * 16 + jj) * 32;
#pragma unroll
            for (int d = 0; d < 32; ++d) ffma2(o2[d], p2, vj[d]);
        }
    }

    const float inv = 1.0f / l;
    float ov[64];
#pragma unroll
    for (int d = 0; d < 32; ++d) {
        float lo, hi; upk2(lo, hi, o2[d]);
        ov[2*d]   = lo * inv;
        ov[2*d+1] = hi * inv;
    }

    // bf16 hi/lo split, row-major [M_TOK, 1024]
    const size_t obase = ((size_t)(w * WIN + tid) * HDIM + hd_i * HD) >> 3;
#pragma unroll
    for (int c8 = 0; c8 < 8; ++c8) {
        U8 H, L;
#pragma unroll
        for (int j = 0; j < 8; ++j) {
            float v = ov[c8 * 8 + j];
            __nv_bfloat16 hb = __float2bfloat16(v);
            H.b[j] = hb;
            L.b[j] = __float2bfloat16(v - __bfloat162float(hb));
        }
        oh[obase + c8] = H.q;
        ol[obase + c8] = L.q;
    }
}

// ---------------------------------------------------------------------------
extern "C" void kernel_launch(void* const* d_in, const int* in_sizes, int n_in,
                              void* d_out, int out_size)
{
    (void)in_sizes; (void)n_in; (void)out_size;
    const float* x     = (const float*)d_in[0];
    const float* w_in  = (const float*)d_in[1];
    const float* b_in  = (const float*)d_in[2];
    const float* w_out = (const float*)d_in[3];
    const float* b_out = (const float*)d_in[4];
    float* out = (float*)d_out;

    float* qkv;
    uint4 *xh, *xl, *wih, *wil, *woh, *wol, *ah, *al;
    cudaGetSymbolAddress((void**)&qkv, g_qkv);
    cudaGetSymbolAddress((void**)&xh,  g_xh);
    cudaGetSymbolAddress((void**)&xl,  g_xl);
    cudaGetSymbolAddress((void**)&wih, g_wih);
    cudaGetSymbolAddress((void**)&wil, g_wil);
    cudaGetSymbolAddress((void**)&woh, g_woh);
    cudaGetSymbolAddress((void**)&wol, g_wol);
    cudaGetSymbolAddress((void**)&ah,  g_ah);
    cudaGetSymbolAddress((void**)&al,  g_al);

    cudaFuncSetAttribute(gemm_mma,
                         cudaFuncAttributeMaxDynamicSharedMemorySize, GEMM_SMEM);
    cudaFuncSetAttribute(attn_kernel,
                         cudaFuncAttributeMaxDynamicSharedMemorySize, ATTN_SMEM);

    // split fp32 inputs into bf16 hi/lo (row-major)
    split_rm<<<(M_TOK  * HDIM) / 2048, 256>>>((const float4*)x,     xh,  xl);
    split_rm<<<(QKVDIM * HDIM) / 2048, 256>>>((const float4*)w_in,  wih, wil);
    split_rm<<<(HDIM   * HDIM) / 2048, 256>>>((const float4*)w_out, woh, wol);

    // Stage 1: QKV projection
    gemm_mma<<<dim3(M_TOK / 128, QKVDIM / 128), 256, GEMM_SMEM>>>(
        (const __nv_bfloat16*)xh, (const __nv_bfloat16*)xl,
        (const __nv_bfloat16*)wih, (const __nv_bfloat16*)wil,
        b_in, qkv, QKVDIM);

    // Stage 2: windowed attention (online softmax, emits bf16 hi/lo)
    attn_kernel<<<dim3(NWIN, NHEAD), 128, ATTN_SMEM>>>(qkv, ah, al);

    // Stage 3: output projection
    gemm_mma<<<dim3(M_TOK / 128, HDIM / 128), 256, GEMM_SMEM>>>(
        (const __nv_bfloat16*)ah, (const __nv_bfloat16*)al,
        (const __nv_bfloat16*)woh, (const __nv_bfloat16*)wol,
        b_out, out, HDIM);
}

// round 8
// speedup vs baseline: 1.0032x; 1.0003x over previous
#include <cuda_runtime.h>
#include <cuda_bf16.h>
#include <cstdint>

// ---------------------------------------------------------------------------
// LocalWindowTransformer on sm_103 (mma.sync HMMA path).
//   GEMM1: qkv = x @ Win^T + b_in   [16384 x 3072], K=1024
//   attn : per (window, head) online-softmax(qk^T/8)v  (fp32 FFMA2)
//   GEMM3: out = att @ Wout^T + b_out [16384 x 1024], K=1024
// fp32 GEMM emulated with bf16 3-split: A_hi*B_hi + A_hi*B_lo + A_lo*B_hi,
// fp32 accumulate in mma.sync.m16n8k16.row.col.f32.bf16.bf16.f32.
// R4: 3-stage cp.async pipeline (1 barrier/tile), flash-style attention.
// ---------------------------------------------------------------------------

#define M_TOK   16384
#define HDIM    1024
#define QKVDIM  3072
#define NHEAD   16
#define HD      64
#define WIN     128
#define NWIN    128

// ---- device scratch (no cudaMalloc allowed) --------------------------------
__device__ float  g_qkv [(size_t)M_TOK * QKVDIM];          // 192 MiB fp32
__device__ uint4  g_xh  [(size_t)M_TOK * HDIM / 8];        // 32 MiB bf16
__device__ uint4  g_xl  [(size_t)M_TOK * HDIM / 8];
__device__ uint4  g_wih [(size_t)QKVDIM * HDIM / 8];       // 6 MiB
__device__ uint4  g_wil [(size_t)QKVDIM * HDIM / 8];
__device__ uint4  g_woh [(size_t)HDIM * HDIM / 8];         // 2 MiB
__device__ uint4  g_wol [(size_t)HDIM * HDIM / 8];
__device__ uint4  g_ah  [(size_t)M_TOK * HDIM / 8];        // 32 MiB (attn out)
__device__ uint4  g_al  [(size_t)M_TOK * HDIM / 8];

// ---- helpers ---------------------------------------------------------------
__device__ __forceinline__ uint32_t smem_u32(const void* p) {
    uint32_t a;
    asm("{ .reg .u64 t; cvta.to.shared.u64 t, %1; cvt.u32.u64 %0, t; }"
        : "=r"(a) : "l"(p));
    return a;
}
__device__ __forceinline__ void cp16(uint32_t dst, const void* src) {
    asm volatile("cp.async.cg.shared.global [%0], [%1], 16;"
                 :: "r"(dst), "l"(src));
}

#define LDSM4(r, a) \
    asm volatile("ldmatrix.sync.aligned.m8n8.x4.shared.b16 {%0,%1,%2,%3}, [%4];" \
                 : "=r"((r)[0]), "=r"((r)[1]), "=r"((r)[2]), "=r"((r)[3]) \
                 : "r"(a))

#define MMA(c, a, b0, b1) \
    asm volatile("mma.sync.aligned.m16n8k16.row.col.f32.bf16.bf16.f32 " \
                 "{%0,%1,%2,%3}, {%4,%5,%6,%7}, {%8,%9}, {%0,%1,%2,%3};" \
                 : "+f"((c)[0]), "+f"((c)[1]), "+f"((c)[2]), "+f"((c)[3]) \
                 : "r"((a)[0]), "r"((a)[1]), "r"((a)[2]), "r"((a)[3]), \
                   "r"(b0), "r"(b1))

union U8 { uint4 q; __nv_bfloat16 b[8]; };

// ---------------------------------------------------------------------------
// split fp32 row-major -> bf16 hi/lo row-major. 1 thread = 8 values.
// ---------------------------------------------------------------------------
__global__ __launch_bounds__(256)
void split_rm(const float4* __restrict__ src,
              uint4* __restrict__ hi, uint4* __restrict__ lo)
{
    int u = blockIdx.x * 256 + threadIdx.x;
    float4 a = src[2 * u], b = src[2 * u + 1];
    float v[8] = {a.x, a.y, a.z, a.w, b.x, b.y, b.z, b.w};
    U8 H, L;
#pragma unroll
    for (int j = 0; j < 8; ++j) {
        __nv_bfloat16 hb = __float2bfloat16(v[j]);
        H.b[j] = hb;
        L.b[j] = __float2bfloat16(v[j] - __bfloat162float(hb));
    }
    hi[u] = H.q;
    lo[u] = L.q;
}

// ---------------------------------------------------------------------------
// HMMA NT GEMM: C[M,N] = A[M,1024] * B[N,1024]^T + bias (fp32 via bf16 split)
// BM=BN=128, BK=32, 256 threads (8 warps, 2x4), warp tile 64x32.
// smem rows padded to 80B. 3-stage cp.async pipeline, ONE barrier per tile.
// ---------------------------------------------------------------------------
#define ARR    10240            /* one 128x32 bf16 array, 80B rows */
#define STAGE  40960            /* Ah|Al|Bh|Bl */
#define KT     32               /* 1024 / 32 */
#define GEMM_SMEM (3 * STAGE)   /* 122880 B */

__global__ __launch_bounds__(256, 1)
void gemm_mma(const __nv_bfloat16* __restrict__ Ah,
              const __nv_bfloat16* __restrict__ Al,
              const __nv_bfloat16* __restrict__ Bh,
              const __nv_bfloat16* __restrict__ Bl,
              const float* __restrict__ bias,
              float* __restrict__ C, int N)
{
    extern __shared__ char smem_raw[];
    const uint32_t sb = smem_u32(smem_raw);

    const int tid  = threadIdx.x;
    const int lane = tid & 31;
    const int wid  = tid >> 5;
    const int wm   = wid & 1;           // 0..1  (64-row halves)
    const int wn   = wid >> 1;          // 0..3  (32-col quarters)
    const int bm   = blockIdx.x;
    const int bn   = blockIdx.y;

    // --- per-thread load slots: 2 units per array, unit = 16B ---
    const int r0 = tid >> 2;                 // rows 0..63
    const int r1 = r0 + 64;                  // rows 64..127
    const int ce = (tid & 3) * 8;            // bf16 element offset of chunk
    const uint32_t d0 = r0 * 80 + (tid & 3) * 16;
    const uint32_t d1 = r1 * 80 + (tid & 3) * 16;

    const __nv_bfloat16* pAh0 = Ah + (size_t)(bm * 128 + r0) * 1024 + ce;
    const __nv_bfloat16* pAh1 = Ah + (size_t)(bm * 128 + r1) * 1024 + ce;
    const __nv_bfloat16* pAl0 = Al + (size_t)(bm * 128 + r0) * 1024 + ce;
    const __nv_bfloat16* pAl1 = Al + (size_t)(bm * 128 + r1) * 1024 + ce;
    const __nv_bfloat16* pBh0 = Bh + (size_t)(bn * 128 + r0) * 1024 + ce;
    const __nv_bfloat16* pBh1 = Bh + (size_t)(bn * 128 + r1) * 1024 + ce;
    const __nv_bfloat16* pBl0 = Bl + (size_t)(bn * 128 + r0) * 1024 + ce;
    const __nv_bfloat16* pBl1 = Bl + (size_t)(bn * 128 + r1) * 1024 + ce;

    // --- per-thread ldmatrix bases ---
    const uint32_t a_off = (uint32_t)((wm * 64 + (lane & 15)) * 80 + (lane >> 4) * 16);
    const uint32_t b_off = (uint32_t)(2 * ARR + (wn * 32 + (lane & 15)) * 80 + (lane >> 4) * 16);

    float acc[4][4][4];
#pragma unroll
    for (int i = 0; i < 4; ++i)
#pragma unroll
        for (int j = 0; j < 4; ++j)
#pragma unroll
            for (int k = 0; k < 4; ++k) acc[i][j][k] = 0.f;

    // --- issue one stage's loads into smem slot ---
    auto issue = [&](uint32_t st, int ko) {
        cp16(st + d0,         pAh0 + ko); cp16(st + d1,         pAh1 + ko);
        cp16(st + ARR + d0,   pAl0 + ko); cp16(st + ARR + d1,   pAl1 + ko);
        cp16(st + 2*ARR + d0, pBh0 + ko); cp16(st + 2*ARR + d1, pBh1 + ko);
        cp16(st + 3*ARR + d0, pBl0 + ko); cp16(st + 3*ARR + d1, pBl1 + ko);
    };

    // prologue: stages 0 and 1
    issue(sb, 0);
    asm volatile("cp.async.commit_group;" ::: "memory");
    issue(sb + STAGE, 32);
    asm volatile("cp.async.commit_group;" ::: "memory");

    int cs = 0;       // compute slot
    int ws = 2;       // write slot (stage t+2)
    for (int t = 0; t < KT; ++t) {
        // stage t arrived (newest pending group allowed: stage t+1)
        asm volatile("cp.async.wait_group 1;" ::: "memory");
        __syncthreads();   // all warps done with stage t-1's slot; data visible

        if (t + 2 < KT)
            issue(sb + ws * STAGE, (t + 2) * 32);
        asm volatile("cp.async.commit_group;" ::: "memory");
        ws = (ws == 2) ? 0 : ws + 1;

        const uint32_t st = sb + cs * STAGE;
        cs = (cs == 2) ? 0 : cs + 1;
        const uint32_t ab = st + a_off;
        const uint32_t bb = st + b_off;
#pragma unroll
        for (int ks = 0; ks < 2; ++ks) {
            uint32_t ah[4][4], al[4][4], bh[2][4], bl[2][4];
#pragma unroll
            for (int mt = 0; mt < 4; ++mt) {
                LDSM4(ah[mt], ab + mt * 1280 + ks * 32);
                LDSM4(al[mt], ab + ARR + mt * 1280 + ks * 32);
            }
#pragma unroll
            for (int np = 0; np < 2; ++np) {
                LDSM4(bh[np], bb + np * 1280 + ks * 32);
                LDSM4(bl[np], bb + ARR + np * 1280 + ks * 32);
            }
#pragma unroll
            for (int mt = 0; mt < 4; ++mt) {
#pragma unroll
                for (int nt = 0; nt < 4; ++nt) {
                    const int np = nt >> 1, s = nt & 1;
                    MMA(acc[mt][nt], ah[mt], bh[np][s], bh[np][s + 2]);
                    MMA(acc[mt][nt], ah[mt], bl[np][s], bl[np][s + 2]);
                    MMA(acc[mt][nt], al[mt], bh[np][s], bh[np][s + 2]);
                }
            }
        }
    }

    // --- epilogue: register frags -> GMEM with bias ---
#pragma unroll
    for (int mt = 0; mt < 4; ++mt) {
#pragma unroll
        for (int nt = 0; nt < 4; ++nt) {
            const float* c = acc[mt][nt];
            const int row = bm * 128 + wm * 64 + mt * 16 + (lane >> 2);
            const int col = bn * 128 + wn * 32 + nt * 8 + (lane & 3) * 2;
            const float b0 = __ldg(bias + col);
            const float b1 = __ldg(bias + col + 1);
            *(float2*)(C + (size_t)row * N + col) =
                make_float2(c[0] + b0, c[1] + b1);
            *(float2*)(C + (size_t)(row + 8) * N + col) =
                make_float2(c[2] + b0, c[3] + b1);
        }
    }
}

// ---------------------------------------------------------------------------
// Windowed attention: online (chunked flash) softmax, fp32 packed-f32x2 math.
// One CTA per (window, head), 128 threads, thread = query row. smem = K+V only
// (64 KB) -> up to 3 CTAs/SM.
// ---------------------------------------------------------------------------
__device__ __forceinline__ unsigned long long pk2(float lo, float hi) {
    unsigned long long r;
    asm("mov.b64 %0, {%1, %2};" : "=l"(r) : "f"(lo), "f"(hi));
    return r;
}
__device__ __forceinline__ void upk2(float& lo, float& hi, unsigned long long v) {
    asm("mov.b64 {%0, %1}, %2;" : "=f"(lo), "=f"(hi) : "l"(v));
}
__device__ __forceinline__ void ffma2(unsigned long long& c,
                                      unsigned long long a,
                                      unsigned long long b) {
    asm("fma.rn.f32x2 %0, %1, %2, %0;" : "+l"(c) : "l"(a), "l"(b));
}
__device__ __forceinline__ void fmul2(unsigned long long& c,
                                      unsigned long long a) {
    asm("mul.rn.f32x2 %0, %0, %1;" : "+l"(c) : "l"(a));
}

#define ATTN_SMEM ((8192 + 8192) * 4)

__global__ __launch_bounds__(128)
void attn_kernel(const float* __restrict__ qkv,
                 uint4* __restrict__ oh, uint4* __restrict__ ol)
{
    extern __shared__ float sm[];
    float* Ks = sm;               // [128][64]
    float* Vs = sm + 8192;        // [128][64]

    const int w    = blockIdx.x;
    const int hd_i = blockIdx.y;
    const int tid  = threadIdx.x;

    const size_t base = (size_t)w * WIN * QKVDIM;
    const float* Kg = qkv + base + HDIM     + hd_i * HD;
    const float* Vg = qkv + base + 2 * HDIM + hd_i * HD;

    for (int idx = tid; idx < WIN * HD; idx += 128) {
        int row = idx >> 6, d = idx & 63;
        Ks[idx] = Kg[(size_t)row * QKVDIM + d];
        Vs[idx] = Vg[(size_t)row * QKVDIM + d];
    }

    const float4* Qg = (const float4*)(qkv + base + (size_t)tid * QKVDIM + hd_i * HD);
    unsigned long long q2[32];
#pragma unroll
    for (int i = 0; i < 16; ++i) {
        float4 v = Qg[i];
        q2[2*i]   = pk2(v.x, v.y);
        q2[2*i+1] = pk2(v.z, v.w);
    }
    __syncthreads();

    const unsigned long long* K2 = (const unsigned long long*)Ks;
    const unsigned long long* V2 = (const unsigned long long*)Vs;

    float m = -1e30f, l = 0.f;
    unsigned long long o2[32];
#pragma unroll
    for (int d = 0; d < 32; ++d) o2[d] = 0ull;

    for (int c = 0; c < 8; ++c) {             // 8 chunks of 16 keys
        float s[16];
#pragma unroll
        for (int jj = 0; jj < 16; ++jj) {
            const int j = c * 16 + jj;
            unsigned long long a0 = 0, a1 = 0, a2 = 0, a3 = 0;
            const unsigned long long* kj = K2 + j * 32;
#pragma unroll
            for (int d = 0; d < 32; d += 4) {
                ffma2(a0, q2[d+0], kj[d+0]);
                ffma2(a1, q2[d+1], kj[d+1]);
                ffma2(a2, q2[d+2], kj[d+2]);
                ffma2(a3, q2[d+3], kj[d+3]);
            }
            float lo, hi, ss;
            upk2(lo, hi, a0); ss  = lo + hi;
            upk2(lo, hi, a1); ss += lo + hi;
            upk2(lo, hi, a2); ss += lo + hi;
            upk2(lo, hi, a3); ss += lo + hi;
            s[jj] = ss * 0.125f;
        }
        float cm = s[0];
#pragma unroll
        for (int jj = 1; jj < 16; ++jj) cm = fmaxf(cm, s[jj]);
        const float nm = fmaxf(m, cm);
        const float sc = __expf(m - nm);
        m = nm;
        l *= sc;
        const unsigned long long sc2 = pk2(sc, sc);
#pragma unroll
        for (int d = 0; d < 32; ++d) fmul2(o2[d], sc2);
#pragma unroll
        for (int jj = 0; jj < 16; ++jj) {
            const float p = __expf(s[jj] - nm);
            l += p;
            const unsigned long long p2 = pk2(p, p);
            const unsigned long long* vj = V2 + (c * 16 + jj) * 32;
#pragma unroll
            for (int d = 0; d < 32; ++d) ffma2(o2[d], p2, vj[d]);
        }
    }

    const float inv = 1.0f / l;
    float ov[64];
#pragma unroll
    for (int d = 0; d < 32; ++d) {
        float lo, hi; upk2(lo, hi, o2[d]);
        ov[2*d]   = lo * inv;
        ov[2*d+1] = hi * inv;
    }

    // bf16 hi/lo split, row-major [M_TOK, 1024]
    const size_t obase = ((size_t)(w * WIN + tid) * HDIM + hd_i * HD) >> 3;
#pragma unroll
    for (int c8 = 0; c8 < 8; ++c8) {
        U8 H, L;
#pragma unroll
        for (int j = 0; j < 8; ++j) {
            float v = ov[c8 * 8 + j];
            __nv_bfloat16 hb = __float2bfloat16(v);
            H.b[j] = hb;
            L.b[j] = __float2bfloat16(v - __bfloat162float(hb));
        }
        oh[obase + c8] = H.q;
        ol[obase + c8] = L.q;
    }
}

// ---------------------------------------------------------------------------
extern "C" void kernel_launch(void* const* d_in, const int* in_sizes, int n_in,
                              void* d_out, int out_size)
{
    (void)in_sizes; (void)n_in; (void)out_size;
    const float* x     = (const float*)d_in[0];
    const float* w_in  = (const float*)d_in[1];
    const float* b_in  = (const float*)d_in[2];
    const float* w_out = (const float*)d_in[3];
    const float* b_out = (const float*)d_in[4];
    float* out = (float*)d_out;

    float* qkv;
    uint4 *xh, *xl, *wih, *wil, *woh, *wol, *ah, *al;
    cudaGetSymbolAddress((void**)&qkv, g_qkv);
    cudaGetSymbolAddress((void**)&xh,  g_xh);
    cudaGetSymbolAddress((void**)&xl,  g_xl);
    cudaGetSymbolAddress((void**)&wih, g_wih);
    cudaGetSymbolAddress((void**)&wil, g_wil);
    cudaGetSymbolAddress((void**)&woh, g_woh);
    cudaGetSymbolAddress((void**)&wol, g_wol);
    cudaGetSymbolAddress((void**)&ah,  g_ah);
    cudaGetSymbolAddress((void**)&al,  g_al);

    cudaFuncSetAttribute(gemm_mma,
                         cudaFuncAttributeMaxDynamicSharedMemorySize, GEMM_SMEM);
    cudaFuncSetAttribute(attn_kernel,
                         cudaFuncAttributeMaxDynamicSharedMemorySize, ATTN_SMEM);

    // split fp32 inputs into bf16 hi/lo (row-major)
    split_rm<<<(M_TOK  * HDIM) / 2048, 256>>>((const float4*)x,     xh,  xl);
    split_rm<<<(QKVDIM * HDIM) / 2048, 256>>>((const float4*)w_in,  wih, wil);
    split_rm<<<(HDIM   * HDIM) / 2048, 256>>>((const float4*)w_out, woh, wol);

    // Stage 1: QKV projection
    gemm_mma<<<dim3(M_TOK / 128, QKVDIM / 128), 256, GEMM_SMEM>>>(
        (const __nv_bfloat16*)xh, (const __nv_bfloat16*)xl,
        (const __nv_bfloat16*)wih, (const __nv_bfloat16*)wil,
        b_in, qkv, QKVDIM);

    // Stage 2: windowed attention (online softmax, emits bf16 hi/lo)
    attn_kernel<<<dim3(NWIN, NHEAD), 128, ATTN_SMEM>>>(qkv, ah, al);

    // Stage 3: output projection
    gemm_mma<<<dim3(M_TOK / 128, HDIM / 128), 256, GEMM_SMEM>>>(
        (const __nv_bfloat16*)ah, (const __nv_bfloat16*)al,
        (const __nv_bfloat16*)woh, (const __nv_bfloat16*)wol,
        b_out, out, HDIM);
}